// round 4
// baseline (speedup 1.0000x reference)
#include <cuda_runtime.h>

// VanillaRNN: B=128, S=2048, E=256, H=512, V=128, fp32.
// Persistent kernel: 128 CTAs (one per SM-slot, all co-resident), software
// grid barrier per timestep. Each CTA owns a (32 B-rows x 16 H-cols) tile of
// the hidden state plus 4 V-cols of the output projection. Weights are held
// transposed in SMEM for the whole kernel; per step only the 32x512 h slice
// is re-read from L2 (__ldcg). Input projection (emb gather @ Wx) is computed
// on the fly each step. Compute uses fma.rn.f32x2 packed FMAs with split-K
// (16 slices) + 8x4 register microtiles, reduced through SMEM.

#define Bb   128
#define Ss   2048
#define Vv   128
#define Ee   256
#define Hh   512
#define NBLK 128
#define NTHR 256

// Padded SMEM row strides (floats). 516 floats = 129 sixteen-byte units (odd)
// keeps adjacent rows on distinct bank groups while preserving float4 alignment.
#define PW   516
#define PWX  260

// SMEM layout (floats)
#define OFF_SH    0                       // h tile: 32 x PW
#define OFF_WH    (32*PW)                 // WhT: 16 x PW
#define OFF_WX    (OFF_WH + 16*PW)        // WxT: 16 x PWX
#define OFF_WF    (OFF_WX + 16*PWX)       // WfcT: 4 x PW
#define OFF_RR    (OFF_WF + 4*PW)         // rec partials: 16 x 520
#define OFF_RV    (OFF_RR + 16*520)       // out partials: 16 x 136
#define OFF_BH    (OFF_RV + 16*136)       // 16
#define OFF_BFC   (OFF_BH + 16)           // 4
#define OFF_TOK   (OFF_BFC + 4)           // 32 ints
#define SMEM_FLOATS (OFF_TOK + 32)
#define SMEM_BYTES  (SMEM_FLOATS * 4)

__device__ float g_h[2][Bb * Hh];   // double-buffered hidden state
__device__ int   g_bar;            // monotonic barrier counter

__device__ __forceinline__ float2 ffma2(float2 a, float2 b, float2 c) {
    union { float2 f; unsigned long long u; } A, B2, C;
    A.f = a; B2.f = b; C.f = c;
    asm("fma.rn.f32x2 %0, %1, %2, %0;" : "+l"(C.u) : "l"(A.u), "l"(B2.u));
    return C.f;
}

__global__ void rnn_init_kernel() {
    int idx = blockIdx.x * blockDim.x + threadIdx.x;
    for (int i = idx; i < Bb * Hh; i += gridDim.x * blockDim.x)
        g_h[1][i] = 0.0f;                 // h_{-1} = 0 (read at t=0)
    if (idx == 0) g_bar = 0;
}

__global__ void __launch_bounds__(NTHR, 1)
rnn_persistent(const int*   __restrict__ x,
               const float* __restrict__ emb,
               const float* __restrict__ Wx,
               const float* __restrict__ bx,
               const float* __restrict__ Wh,
               const float* __restrict__ bh,
               const float* __restrict__ Wfc,
               const float* __restrict__ bfc,
               float* __restrict__ out)
{
    extern __shared__ float sm[];
    float* sh    = sm + OFF_SH;
    float* sWhT  = sm + OFF_WH;
    float* sWxT  = sm + OFF_WX;
    float* sWfcT = sm + OFF_WF;
    float* sredR = sm + OFF_RR;
    float* sredV = sm + OFF_RV;
    float* sbh   = sm + OFF_BH;
    float* sbfc  = sm + OFF_BFC;
    int*   stok  = (int*)(sm + OFF_TOK);

    const int tid = threadIdx.x;
    const int bidx = blockIdx.x;
    const int R0  = (bidx >> 5) << 5;   // 32-row group
    const int cg  = bidx & 31;
    const int C0  = cg << 4;            // 16 H-cols
    const int VC0 = cg << 2;            // 4 V-cols
    // thread -> (k-slice, row-group, col-group). Warp = {2 ks} x {4 ig} x {4 jg}.
    const int ks = tid >> 4;            // 0..15  (K split)
    const int ig = (tid >> 2) & 3;      // rows: i = ig + 4r, r=0..7
    const int jg = tid & 3;             // cols: j = jg + 4jj, jj=0..3

    // ---- prologue: stage transposed weight tiles (persist across all steps)
    for (int idx = tid; idx < 16 * Hh; idx += NTHR) {
        int j = idx & 15, k = idx >> 4;
        sWhT[j * PW + k] = Wh[k * Hh + C0 + j];
    }
    for (int idx = tid; idx < 16 * Ee; idx += NTHR) {
        int j = idx & 15, e = idx >> 4;
        sWxT[j * PWX + e] = Wx[e * Hh + C0 + j];
    }
    for (int idx = tid; idx < 4 * Hh; idx += NTHR) {
        int j = idx & 3, k = idx >> 2;
        sWfcT[j * PW + k] = Wfc[k * Vv + VC0 + j];
    }
    if (tid < 16) sbh[tid]  = bh[C0 + tid] + bx[C0 + tid];
    if (tid < 4)  sbfc[tid] = bfc[VC0 + tid];

    const float* hrow[8];
    const float* wrow[4];
    const float* xwrow[4];
#pragma unroll
    for (int r = 0; r < 8; ++r)  hrow[r]  = sh + (ig + (r << 2)) * PW;
#pragma unroll
    for (int jj = 0; jj < 4; ++jj) {
        wrow[jj]  = sWhT + (jg + (jj << 2)) * PW;
        xwrow[jj] = sWxT + (jg + (jj << 2)) * PWX;
    }
    const float* wfrow = sWfcT + jg * PW;

    for (int t = 0; t <= Ss; ++t) {
        // ---- stage h_{t-1} tile (L2 via ldcg: cross-CTA coherence) + tokens
        const float* hsrc = g_h[(t + 1) & 1];
#pragma unroll
        for (int q = 0; q < 16; ++q) {
            int u  = tid + (q << 8);        // float4 index 0..4095
            int i  = u >> 7;                // row 0..31
            int un = u & 127;               // 16B unit in row
            float4 v = __ldcg(((const float4*)(hsrc + ((R0 + i) << 9))) + un);
            *(float4*)(sh + i * PW + (un << 2)) = v;
        }
        if (t < Ss && tid < 32) stok[tid] = x[(R0 + tid) * Ss + t];
        __syncthreads();

        float2 accV[8];
#pragma unroll
        for (int r = 0; r < 8; ++r) accV[r] = make_float2(0.f, 0.f);

        if (t < Ss) {
            float2 accR[8][4];
#pragma unroll
            for (int r = 0; r < 8; ++r)
#pragma unroll
                for (int jj = 0; jj < 4; ++jj) accR[r][jj] = make_float2(0.f, 0.f);

            // ---- recurrence (K=512) fused with output proj of h_{t-1}
#pragma unroll
            for (int m = 0; m < 8; ++m) {
                const int k = (ks + (m << 4)) << 2;   // interleaved chunks
                float4 h4[8];
#pragma unroll
                for (int r = 0; r < 8; ++r)
                    h4[r] = *(const float4*)(hrow[r] + k);
                const float4 wf = *(const float4*)(wfrow + k);
#pragma unroll
                for (int jj = 0; jj < 4; ++jj) {
                    const float4 w = *(const float4*)(wrow[jj] + k);
#pragma unroll
                    for (int r = 0; r < 8; ++r) {
                        accR[r][jj] = ffma2(make_float2(h4[r].x, h4[r].y),
                                            make_float2(w.x, w.y), accR[r][jj]);
                        accR[r][jj] = ffma2(make_float2(h4[r].z, h4[r].w),
                                            make_float2(w.z, w.w), accR[r][jj]);
                    }
                }
#pragma unroll
                for (int r = 0; r < 8; ++r) {
                    accV[r] = ffma2(make_float2(h4[r].x, h4[r].y),
                                    make_float2(wf.x, wf.y), accV[r]);
                    accV[r] = ffma2(make_float2(h4[r].z, h4[r].w),
                                    make_float2(wf.z, wf.w), accV[r]);
                }
            }

            // ---- input projection (emb gather @ Wx), K=256
            int tok[8];
#pragma unroll
            for (int r = 0; r < 8; ++r) tok[r] = stok[ig + (r << 2)];
#pragma unroll
            for (int m = 0; m < 4; ++m) {
                const int e = (ks + (m << 4)) << 2;
                float4 x4[8];
#pragma unroll
                for (int r = 0; r < 8; ++r)
                    x4[r] = __ldg(((const float4*)(emb + tok[r] * Ee)) + (e >> 2));
#pragma unroll
                for (int jj = 0; jj < 4; ++jj) {
                    const float4 w = *(const float4*)(xwrow[jj] + e);
#pragma unroll
                    for (int r = 0; r < 8; ++r) {
                        accR[r][jj] = ffma2(make_float2(x4[r].x, x4[r].y),
                                            make_float2(w.x, w.y), accR[r][jj]);
                        accR[r][jj] = ffma2(make_float2(x4[r].z, x4[r].w),
                                            make_float2(w.z, w.w), accR[r][jj]);
                    }
                }
            }

            // ---- write recurrence partials
#pragma unroll
            for (int r = 0; r < 8; ++r) {
                const int i = ig + (r << 2);
#pragma unroll
                for (int jj = 0; jj < 4; ++jj)
                    sredR[ks * 520 + (i << 4) + jg + (jj << 2)] =
                        accR[r][jj].x + accR[r][jj].y;
            }
        } else {
            // t == S: output projection of h_{S-1} only
#pragma unroll
            for (int m = 0; m < 8; ++m) {
                const int k = (ks + (m << 4)) << 2;
                const float4 wf = *(const float4*)(wfrow + k);
#pragma unroll
                for (int r = 0; r < 8; ++r) {
                    const float4 h = *(const float4*)(hrow[r] + k);
                    accV[r] = ffma2(make_float2(h.x, h.y),
                                    make_float2(wf.x, wf.y), accV[r]);
                    accV[r] = ffma2(make_float2(h.z, h.w),
                                    make_float2(wf.z, wf.w), accV[r]);
                }
            }
        }

        if (t > 0) {
#pragma unroll
            for (int r = 0; r < 8; ++r) {
                const int i = ig + (r << 2);
                sredV[ks * 136 + (i << 2) + jg] = accV[r].x + accV[r].y;
            }
        }
        __syncthreads();

        // ---- reduce 16 K-slices, finalize h_t and out[:, t-1, :]
        if (t < Ss) {
#pragma unroll
            for (int q = 0; q < 2; ++q) {
                const int o = (tid << 1) + q;       // 0..511
                const int i = o >> 4, j = o & 15;
                float s = sbh[j];
#pragma unroll
                for (int kk = 0; kk < 16; ++kk) s += sredR[kk * 520 + o];
                s = tanhf(s);
                g_h[t & 1][((R0 + i) << 9) + C0 + j] = s;
            }
        }
        if (t > 0 && tid < 128) {
            const int i = tid >> 2, j = tid & 3;
            float s = sbfc[j];
#pragma unroll
            for (int kk = 0; kk < 16; ++kk) s += sredV[kk * 136 + tid];
            out[(R0 + i) * (Ss * Vv) + (t - 1) * Vv + VC0 + j] = s;
        }

        // ---- grid barrier (release: fence + atomic arrive; acquire: ld.acquire)
        if (t < Ss) {
            __threadfence();
            __syncthreads();
            if (tid == 0) {
                atomicAdd(&g_bar, 1);
                const int target = NBLK * (t + 1);
                int v;
                do {
                    asm volatile("ld.acquire.gpu.global.b32 %0, [%1];"
                                 : "=r"(v) : "l"(&g_bar) : "memory");
                    if (v >= target) break;
                    __nanosleep(128);
                } while (true);
            }
            __syncthreads();
        }
    }
}

extern "C" void kernel_launch(void* const* d_in, const int* in_sizes, int n_in,
                              void* d_out, int out_size) {
    const int*   x   = (const int*)  d_in[0];
    const float* emb = (const float*)d_in[1];
    const float* Wx  = (const float*)d_in[2];
    const float* bx  = (const float*)d_in[3];
    const float* Wh  = (const float*)d_in[4];
    const float* bh  = (const float*)d_in[5];
    const float* Wfc = (const float*)d_in[6];
    const float* bfc = (const float*)d_in[7];
    float* out = (float*)d_out;

    cudaFuncSetAttribute(rnn_persistent,
                         cudaFuncAttributeMaxDynamicSharedMemorySize, SMEM_BYTES);

    rnn_init_kernel<<<64, 256>>>();
    rnn_persistent<<<NBLK, NTHR, SMEM_BYTES>>>(x, emb, Wx, bx, Wh, bh, Wfc, bfc, out);
}